// round 1
// baseline (speedup 1.0000x reference)
#include <cuda_runtime.h>

// Problem: B=1, H=W=D=128.
// dti: (6, 128,128,128) f32 ; ddf: (3, 128,128,128) f32 ; out: (6, 128,128,128) f32
#define NV (128*128*128)

__device__ __forceinline__ int lin3(int x, int y, int z) {
    return (x << 14) | (y << 7) | z;
}

__global__ __launch_bounds__(256)
void warp_dti_kernel(const float* __restrict__ dti,
                     const float* __restrict__ ddf,
                     float* __restrict__ out)
{
    const int v = blockIdx.x * 256 + threadIdx.x;   // grid exactly covers NV
    const int z = v & 127;
    const int y = (v >> 7) & 127;
    const int x = v >> 14;

    // ---------------- displacement at this voxel ----------------
    const float dx = ddf[v];
    const float dy = ddf[NV + v];
    const float dz = ddf[2 * NV + v];

    // ---------------- trilinear warp coords (border clamp) ----------------
    float cx = fminf(fmaxf((float)x + dx, 0.0f), 127.0f);
    float cy = fminf(fmaxf((float)y + dy, 0.0f), 127.0f);
    float cz = fminf(fmaxf((float)z + dz, 0.0f), 127.0f);

    float x0f = floorf(cx), y0f = floorf(cy), z0f = floorf(cz);
    float fx = cx - x0f, fy = cy - y0f, fz = cz - z0f;
    int x0 = (int)x0f, y0 = (int)y0f, z0 = (int)z0f;
    int x1 = min(x0 + 1, 127), y1 = min(y0 + 1, 127), z1 = min(z0 + 1, 127);

    const int i000 = lin3(x0, y0, z0);
    const int i001 = lin3(x0, y0, z1);
    const int i010 = lin3(x0, y1, z0);
    const int i011 = lin3(x0, y1, z1);
    const int i100 = lin3(x1, y0, z0);
    const int i101 = lin3(x1, y0, z1);
    const int i110 = lin3(x1, y1, z0);
    const int i111 = lin3(x1, y1, z1);

    const float gx0 = 1.0f - fx, gy0 = 1.0f - fy, gz0 = 1.0f - fz;
    const float w000 = gx0 * gy0 * gz0;
    const float w001 = gx0 * gy0 * fz;
    const float w010 = gx0 * fy  * gz0;
    const float w011 = gx0 * fy  * fz;
    const float w100 = fx  * gy0 * gz0;
    const float w101 = fx  * gy0 * fz;
    const float w110 = fx  * fy  * gz0;
    const float w111 = fx  * fy  * fz;

    float m[6];
    #pragma unroll
    for (int c = 0; c < 6; c++) {
        const float* p = dti + c * NV;
        float a = w000 * p[i000];
        a = fmaf(w001, p[i001], a);
        a = fmaf(w010, p[i010], a);
        a = fmaf(w011, p[i011], a);
        a = fmaf(w100, p[i100], a);
        a = fmaf(w101, p[i101], a);
        a = fmaf(w110, p[i110], a);
        a = fmaf(w111, p[i111], a);
        m[c] = a;
    }

    // ---------------- Jacobian J = I + d(ddf)/dx (jnp.gradient semantics) ----
    const int xp = min(x + 1, 127), xm = max(x - 1, 0);
    const int yp = min(y + 1, 127), ym = max(y - 1, 0);
    const int zp = min(z + 1, 127), zm = max(z - 1, 0);
    const float sx = (xp - xm == 2) ? 0.5f : 1.0f;
    const float sy = (yp - ym == 2) ? 0.5f : 1.0f;
    const float sz = (zp - zm == 2) ? 0.5f : 1.0f;

    const int ixp = lin3(xp, y, z), ixm = lin3(xm, y, z);
    const int iyp = lin3(x, yp, z), iym = lin3(x, ym, z);
    const int izp = lin3(x, y, zp), izm = lin3(x, y, zm);

    float X[3][3];
    #pragma unroll
    for (int i = 0; i < 3; i++) {
        const float* p = ddf + i * NV;
        X[i][0] = (p[ixp] - p[ixm]) * sx;
        X[i][1] = (p[iyp] - p[iym]) * sy;
        X[i][2] = (p[izp] - p[izm]) * sz;
    }
    X[0][0] += 1.0f;
    X[1][1] += 1.0f;
    X[2][2] += 1.0f;

    // ---------------- polar factor via scaled Newton iteration --------------
    // X_{k+1} = 0.5 * (mu * X + (1/mu) * X^{-T}),  mu = (||X^{-1}||F/||X||F)^{1/2}
    // Converges quadratically to R = U Vh (the SVD polar factor), any det sign.
    #pragma unroll
    for (int it = 0; it < 8; it++) {
        // Cofactor matrix C (X^{-T} = C / det)
        float C00 = X[1][1] * X[2][2] - X[1][2] * X[2][1];
        float C01 = X[1][2] * X[2][0] - X[1][0] * X[2][2];
        float C02 = X[1][0] * X[2][1] - X[1][1] * X[2][0];
        float C10 = X[0][2] * X[2][1] - X[0][1] * X[2][2];
        float C11 = X[0][0] * X[2][2] - X[0][2] * X[2][0];
        float C12 = X[0][1] * X[2][0] - X[0][0] * X[2][1];
        float C20 = X[0][1] * X[1][2] - X[0][2] * X[1][1];
        float C21 = X[0][2] * X[1][0] - X[0][0] * X[1][2];
        float C22 = X[0][0] * X[1][1] - X[0][1] * X[1][0];

        float det = X[0][0] * C00 + X[0][1] * C01 + X[0][2] * C02;
        float ad = fabsf(det);
        det = (ad < 1e-30f) ? ((det < 0.0f) ? -1e-30f : 1e-30f) : det;
        float rdet = __frcp_rn(det);

        // Frobenius norms for optimal scaling
        float a2 = X[0][0]*X[0][0] + X[0][1]*X[0][1] + X[0][2]*X[0][2]
                 + X[1][0]*X[1][0] + X[1][1]*X[1][1] + X[1][2]*X[1][2]
                 + X[2][0]*X[2][0] + X[2][1]*X[2][1] + X[2][2]*X[2][2];
        float c2s = C00*C00 + C01*C01 + C02*C02
                  + C10*C10 + C11*C11 + C12*C12
                  + C20*C20 + C21*C21 + C22*C22;
        // ||Y||^2 = ||C||^2 * rdet^2 ;  r = ||Y||^2/||X||^2
        float r = (c2s * rdet * rdet) * __frcp_rn(a2);
        float s = sqrtf(r);          // ||Y||/||X||
        float mu  = sqrtf(s);        // r^{1/4}
        float imu = rsqrtf(s);       // r^{-1/4}
        float ca = 0.5f * mu;
        float cb = 0.5f * imu * rdet;

        X[0][0] = ca * X[0][0] + cb * C00;
        X[0][1] = ca * X[0][1] + cb * C01;
        X[0][2] = ca * X[0][2] + cb * C02;
        X[1][0] = ca * X[1][0] + cb * C10;
        X[1][1] = ca * X[1][1] + cb * C11;
        X[1][2] = ca * X[1][2] + cb * C12;
        X[2][0] = ca * X[2][0] + cb * C20;
        X[2][1] = ca * X[2][1] + cb * C21;
        X[2][2] = ca * X[2][2] + cb * C22;
    }

    // ---------------- Dp = R^T M R, M symmetric from warped channels --------
    // M = [[m0,m1,m3],[m1,m2,m4],[m3,m4,m5]]
    float M00 = m[0], M01 = m[1], M02 = m[3];
    float M11 = m[2], M12 = m[4], M22 = m[5];

    // A = M * R
    float A00 = M00 * X[0][0] + M01 * X[1][0] + M02 * X[2][0];
    float A01 = M00 * X[0][1] + M01 * X[1][1] + M02 * X[2][1];
    float A02 = M00 * X[0][2] + M01 * X[1][2] + M02 * X[2][2];
    float A10 = M01 * X[0][0] + M11 * X[1][0] + M12 * X[2][0];
    float A11 = M01 * X[0][1] + M11 * X[1][1] + M12 * X[2][1];
    float A12 = M01 * X[0][2] + M11 * X[1][2] + M12 * X[2][2];
    float A20 = M02 * X[0][0] + M12 * X[1][0] + M22 * X[2][0];
    float A21 = M02 * X[0][1] + M12 * X[1][1] + M22 * X[2][1];
    float A22 = M02 * X[0][2] + M12 * X[1][2] + M22 * X[2][2];

    // Dp[i][l] = sum_j R[j][i] * A[j][l]   (only lower triangle needed)
    float Dp00 = X[0][0] * A00 + X[1][0] * A10 + X[2][0] * A20;
    float Dp10 = X[0][1] * A00 + X[1][1] * A10 + X[2][1] * A20;
    float Dp11 = X[0][1] * A01 + X[1][1] * A11 + X[2][1] * A21;
    float Dp20 = X[0][2] * A00 + X[1][2] * A10 + X[2][2] * A20;
    float Dp21 = X[0][2] * A01 + X[1][2] * A11 + X[2][2] * A21;
    float Dp22 = X[0][2] * A02 + X[1][2] * A12 + X[2][2] * A22;

    out[v]          = Dp00;
    out[NV + v]     = Dp10;
    out[2 * NV + v] = Dp11;
    out[3 * NV + v] = Dp20;
    out[4 * NV + v] = Dp21;
    out[5 * NV + v] = Dp22;
}

extern "C" void kernel_launch(void* const* d_in, const int* in_sizes, int n_in,
                              void* d_out, int out_size)
{
    const float* dti = (const float*)d_in[0];   // 6*128^3
    const float* ddf = (const float*)d_in[1];   // 3*128^3
    float* out = (float*)d_out;                 // 6*128^3
    (void)in_sizes; (void)n_in; (void)out_size;

    dim3 grid(NV / 256);
    warp_dti_kernel<<<grid, 256>>>(dti, ddf, out);
}

// round 2
// speedup vs baseline: 1.1866x; 1.1866x over previous
#include <cuda_runtime.h>

// Problem: B=1, H=W=D=128.
// dti: (6,128,128,128) f32 ; ddf: (3,128,128,128) f32 ; out: (6,128,128,128) f32
#define NV (128*128*128)

__device__ __forceinline__ float frcp_a(float x)  { float r; asm("rcp.approx.f32 %0, %1;"   : "=f"(r) : "f"(x)); return r; }
__device__ __forceinline__ float fsqrt_a(float x) { float r; asm("sqrt.approx.f32 %0, %1;"  : "=f"(r) : "f"(x)); return r; }
__device__ __forceinline__ float frsqrt_a(float x){ float r; asm("rsqrt.approx.f32 %0, %1;" : "=f"(r) : "f"(x)); return r; }

__global__ __launch_bounds__(256)
void warp_dti_kernel(const float* __restrict__ dti,
                     const float* __restrict__ ddf,
                     float* __restrict__ out)
{
    const int v = blockIdx.x * 256 + threadIdx.x;   // grid exactly covers NV
    const int z = v & 127;
    const int y = (v >> 7) & 127;
    const int x = v >> 14;

    // ---------------- displacement at this voxel ----------------
    const float dx = ddf[v];
    const float dy = ddf[NV + v];
    const float dz = ddf[2 * NV + v];

    // ---------------- trilinear warp coords (border clamp) ----------------
    float cx = fminf(fmaxf((float)x + dx, 0.0f), 127.0f);
    float cy = fminf(fmaxf((float)y + dy, 0.0f), 127.0f);
    float cz = fminf(fmaxf((float)z + dz, 0.0f), 127.0f);

    float x0f = floorf(cx), y0f = floorf(cy), z0f = floorf(cz);
    float fx = cx - x0f, fy = cy - y0f, fz = cz - z0f;
    int x0 = (int)x0f, y0 = (int)y0f, z0 = (int)z0f;
    int x1 = min(x0 + 1, 127), y1 = min(y0 + 1, 127), z1 = min(z0 + 1, 127);

    const int base = (x0 << 14) | (y0 << 7) | z0;
    const int ddz = z1 - z0;              // 0 or 1
    const int ddy = (y1 - y0) << 7;
    const int ddx = (x1 - x0) << 14;
    const int i000 = base;
    const int i001 = base + ddz;
    const int i010 = base + ddy;
    const int i011 = base + ddy + ddz;
    const int i100 = base + ddx;
    const int i101 = base + ddx + ddz;
    const int i110 = base + ddx + ddy;
    const int i111 = base + ddx + ddy + ddz;

    const float gx0 = 1.0f - fx, gy0 = 1.0f - fy, gz0 = 1.0f - fz;
    const float w000 = gx0 * gy0 * gz0;
    const float w001 = gx0 * gy0 * fz;
    const float w010 = gx0 * fy  * gz0;
    const float w011 = gx0 * fy  * fz;
    const float w100 = fx  * gy0 * gz0;
    const float w101 = fx  * gy0 * fz;
    const float w110 = fx  * fy  * gz0;
    const float w111 = fx  * fy  * fz;

    float m[6];
    #pragma unroll
    for (int c = 0; c < 6; c++) {
        const float* p = dti + c * NV;
        float a = w000 * p[i000];
        a = fmaf(w001, p[i001], a);
        a = fmaf(w010, p[i010], a);
        a = fmaf(w011, p[i011], a);
        a = fmaf(w100, p[i100], a);
        a = fmaf(w101, p[i101], a);
        a = fmaf(w110, p[i110], a);
        a = fmaf(w111, p[i111], a);
        m[c] = a;
    }

    // ---------------- Jacobian J = I + d(ddf)/dx (jnp.gradient semantics) ----
    const int xp = min(x + 1, 127), xm = max(x - 1, 0);
    const int yp = min(y + 1, 127), ym = max(y - 1, 0);
    const int zp = min(z + 1, 127), zm = max(z - 1, 0);
    // interior: /2, edges: /1   -> s = 1.5 - 0.5*(p - m)
    const float sx = 1.5f - 0.5f * (float)(xp - xm);
    const float sy = 1.5f - 0.5f * (float)(yp - ym);
    const float sz = 1.5f - 0.5f * (float)(zp - zm);

    const int ixp = (xp << 14) | (y << 7) | z;
    const int ixm = (xm << 14) | (y << 7) | z;
    const int iyp = (x << 14) | (yp << 7) | z;
    const int iym = (x << 14) | (ym << 7) | z;
    const int izp = (x << 14) | (y << 7) | zp;
    const int izm = (x << 14) | (y << 7) | zm;

    float X[3][3];
    #pragma unroll
    for (int i = 0; i < 3; i++) {
        const float* p = ddf + i * NV;
        X[i][0] = (p[ixp] - p[ixm]) * sx;
        X[i][1] = (p[iyp] - p[iym]) * sy;
        X[i][2] = (p[izp] - p[izm]) * sz;
    }
    X[0][0] += 1.0f;
    X[1][1] += 1.0f;
    X[2][2] += 1.0f;

    // ---------------- polar factor via Newton iteration ---------------------
    // X <- 0.5*(mu*X + (1/mu)*X^{-T}); Frobenius-optimal mu for the first 3
    // iterations (kills large cond fast), then mu=1 for the last 3.
    #pragma unroll
    for (int it = 0; it < 6; it++) {
        // Cofactor matrix C (X^{-T} = C / det)
        float C00 = X[1][1] * X[2][2] - X[1][2] * X[2][1];
        float C01 = X[1][2] * X[2][0] - X[1][0] * X[2][2];
        float C02 = X[1][0] * X[2][1] - X[1][1] * X[2][0];
        float C10 = X[0][2] * X[2][1] - X[0][1] * X[2][2];
        float C11 = X[0][0] * X[2][2] - X[0][2] * X[2][0];
        float C12 = X[0][1] * X[2][0] - X[0][0] * X[2][1];
        float C20 = X[0][1] * X[1][2] - X[0][2] * X[1][1];
        float C21 = X[0][2] * X[1][0] - X[0][0] * X[1][2];
        float C22 = X[0][0] * X[1][1] - X[0][1] * X[1][0];

        float det = X[0][0] * C00 + X[0][1] * C01 + X[0][2] * C02;
        float ad = fabsf(det);
        det = (ad < 1e-30f) ? ((det < 0.0f) ? -1e-30f : 1e-30f) : det;
        float rdet = frcp_a(det);

        float ca, cb;
        if (it < 3) {
            // Frobenius-optimal scaling: mu = (||X^{-1}||F / ||X||F)^{1/2}
            float a2 = X[0][0]*X[0][0] + X[0][1]*X[0][1] + X[0][2]*X[0][2]
                     + X[1][0]*X[1][0] + X[1][1]*X[1][1] + X[1][2]*X[1][2]
                     + X[2][0]*X[2][0] + X[2][1]*X[2][1] + X[2][2]*X[2][2];
            float c2s = C00*C00 + C01*C01 + C02*C02
                      + C10*C10 + C11*C11 + C12*C12
                      + C20*C20 + C21*C21 + C22*C22;
            float r = (c2s * rdet * rdet) * frcp_a(a2);   // (||Y||/||X||)^2
            float t = fsqrt_a(r);                          // ||Y||/||X||
            float mu  = fsqrt_a(t);                        // r^{1/4}
            float imu = frsqrt_a(t);                       // r^{-1/4}
            ca = 0.5f * mu;
            cb = 0.5f * imu * rdet;
        } else {
            ca = 0.5f;
            cb = 0.5f * rdet;
        }

        X[0][0] = ca * X[0][0] + cb * C00;
        X[0][1] = ca * X[0][1] + cb * C01;
        X[0][2] = ca * X[0][2] + cb * C02;
        X[1][0] = ca * X[1][0] + cb * C10;
        X[1][1] = ca * X[1][1] + cb * C11;
        X[1][2] = ca * X[1][2] + cb * C12;
        X[2][0] = ca * X[2][0] + cb * C20;
        X[2][1] = ca * X[2][1] + cb * C21;
        X[2][2] = ca * X[2][2] + cb * C22;
    }

    // ---------------- Dp = R^T M R, M symmetric from warped channels --------
    float M00 = m[0], M01 = m[1], M02 = m[3];
    float M11 = m[2], M12 = m[4], M22 = m[5];

    // A = M * R
    float A00 = M00 * X[0][0] + M01 * X[1][0] + M02 * X[2][0];
    float A01 = M00 * X[0][1] + M01 * X[1][1] + M02 * X[2][1];
    float A02 = M00 * X[0][2] + M01 * X[1][2] + M02 * X[2][2];
    float A10 = M01 * X[0][0] + M11 * X[1][0] + M12 * X[2][0];
    float A11 = M01 * X[0][1] + M11 * X[1][1] + M12 * X[2][1];
    float A12 = M01 * X[0][2] + M11 * X[1][2] + M12 * X[2][2];
    float A20 = M02 * X[0][0] + M12 * X[1][0] + M22 * X[2][0];
    float A21 = M02 * X[0][1] + M12 * X[1][1] + M22 * X[2][1];
    float A22 = M02 * X[0][2] + M12 * X[1][2] + M22 * X[2][2];

    // Dp[i][l] = sum_j R[j][i] * A[j][l]   (lower triangle only)
    float Dp00 = X[0][0] * A00 + X[1][0] * A10 + X[2][0] * A20;
    float Dp10 = X[0][1] * A00 + X[1][1] * A10 + X[2][1] * A20;
    float Dp11 = X[0][1] * A01 + X[1][1] * A11 + X[2][1] * A21;
    float Dp20 = X[0][2] * A00 + X[1][2] * A10 + X[2][2] * A20;
    float Dp21 = X[0][2] * A01 + X[1][2] * A11 + X[2][2] * A21;
    float Dp22 = X[0][2] * A02 + X[1][2] * A12 + X[2][2] * A22;

    out[v]          = Dp00;
    out[NV + v]     = Dp10;
    out[2 * NV + v] = Dp11;
    out[3 * NV + v] = Dp20;
    out[4 * NV + v] = Dp21;
    out[5 * NV + v] = Dp22;
}

extern "C" void kernel_launch(void* const* d_in, const int* in_sizes, int n_in,
                              void* d_out, int out_size)
{
    const float* dti = (const float*)d_in[0];   // 6*128^3
    const float* ddf = (const float*)d_in[1];   // 3*128^3
    float* out = (float*)d_out;                 // 6*128^3
    (void)in_sizes; (void)n_in; (void)out_size;

    dim3 grid(NV / 256);
    warp_dti_kernel<<<grid, 256>>>(dti, ddf, out);
}